// round 5
// baseline (speedup 1.0000x reference)
#include <cuda_runtime.h>
#include <stdint.h>

// out[b,h,w,:] = graph[b, slic[b,h,w]-1, :]
//   graph: [B=4, S=256, C=128] fp32   -> 128 KiB per batch, cached in smem
//   slic:  [B=4, 512, 512] int32      -> block's 1024 ids also staged in smem
//   out:   [B, 512, 512, 128] fp32    -> 512 MiB coalesced stores = the roofline
//
// Mainloop has NO global loads: broadcast LDS (ids) -> gather LDS -> STG.128.

static constexpr int B  = 4;
static constexpr int S  = 256;
static constexpr int C  = 128;
static constexpr int HW = 512 * 512;                 // 262144
static constexpr int TABLE_FLOATS = S * C;           // 32768 floats = 128 KiB

static constexpr int THREADS        = 1024;          // 32 warps
static constexpr int PIX_PER_BLOCK  = 1024;          // 32 pixels per warp
static constexpr int BLOCKS         = (B * HW) / PIX_PER_BLOCK;  // 1024
static constexpr int SMEM_BYTES     = TABLE_FLOATS * 4 + PIX_PER_BLOCK * 4;  // 132 KiB

__global__ __launch_bounds__(THREADS, 1)
void convert2image_smem_kernel(const float* __restrict__ graph,
                               const int*   __restrict__ slic,
                               float*       __restrict__ out) {
    extern __shared__ float s_table[];               // [S*C] floats = 128 KiB
    int* s_idx = reinterpret_cast<int*>(s_table + TABLE_FLOATS);   // [1024] ints

    const int b = blockIdx.x >> 8;                   // 256 blocks per batch

    // ---- Prologue: stage gather table (coalesced) + this block's slic ids ----
    {
        const float4* gt = reinterpret_cast<const float4*>(graph + (size_t)b * TABLE_FLOATS);
        float4*       st = reinterpret_cast<float4*>(s_table);
        #pragma unroll
        for (int i = 0; i < TABLE_FLOATS / 4 / THREADS; i++)       // 8 iters
            st[threadIdx.x + i * THREADS] = __ldg(&gt[threadIdx.x + i * THREADS]);

        if (threadIdx.x < PIX_PER_BLOCK / 4) {
            const int4* gsl = reinterpret_cast<const int4*>(slic + (size_t)blockIdx.x * PIX_PER_BLOCK);
            reinterpret_cast<int4*>(s_idx)[threadIdx.x] = __ldg(&gsl[threadIdx.x]);
        }
    }
    __syncthreads();

    const int warp = threadIdx.x >> 5;
    const int lane = threadIdx.x & 31;

    const float4* stab  = reinterpret_cast<const float4*>(s_table);           // [S][32] float4
    const int4*   sidx4 = reinterpret_cast<const int4*>(s_idx);               // [256]
    // This warp's 32 contiguous pixels start here:
    const int pix0 = blockIdx.x * PIX_PER_BLOCK + warp * 32;
    float4* dst = reinterpret_cast<float4*>(out) + (size_t)pix0 * 32 + lane;

    #pragma unroll
    for (int step = 0; step < 8; step++) {           // 4 pixels per step
        const int4 iv = sidx4[warp * 8 + step];      // broadcast LDS.128 (uniform)

        // 4 independent conflict-free gathers (all lanes same row, 16B/lane).
        const float4 v0 = stab[(iv.x - 1) * 32 + lane];
        const float4 v1 = stab[(iv.y - 1) * 32 + lane];
        const float4 v2 = stab[(iv.z - 1) * 32 + lane];
        const float4 v3 = stab[(iv.w - 1) * 32 + lane];

        // 4 coalesced 512B stores (2 KiB contiguous per step per warp).
        dst[step * 128 +  0] = v0;
        dst[step * 128 + 32] = v1;
        dst[step * 128 + 64] = v2;
        dst[step * 128 + 96] = v3;
    }
}

extern "C" void kernel_launch(void* const* d_in, const int* in_sizes, int n_in,
                              void* d_out, int out_size) {
    const float* graph = (const float*)d_in[0];
    const int*   slic  = (const int*)d_in[1];
    float*       out   = (float*)d_out;

    static bool attr_set = false;
    if (!attr_set) {
        cudaFuncSetAttribute(convert2image_smem_kernel,
                             cudaFuncAttributeMaxDynamicSharedMemorySize, SMEM_BYTES);
        attr_set = true;
    }

    convert2image_smem_kernel<<<BLOCKS, THREADS, SMEM_BYTES>>>(graph, slic, out);
}